// round 9
// baseline (speedup 1.0000x reference)
#include <cuda_runtime.h>
#include <cuda_fp16.h>
#include <math.h>
#include <stdint.h>

#define NE 50000
#define NN 25000
#define NG 1024
#define HID 128
#define NTILES 391
#define HA_STRIDE ((size_t)NTILES * 32768)

// layer-1 msg smem: A [128x272B] | B buf0 [64x272B] | B buf1
#define SM_B      34816
#define SM_BUF    17408
#define SMEM_BYTES 69632
// o-split msg smem: A [128x272B] | B buf0 [32x272B] | B buf1
#define SM_BUF2   8704
#define SMEM2_BYTES 52224

__device__ __align__(256) unsigned char g_hA[3 * HA_STRIDE];  // per-layer, per-tile fp16 h [128x256B]
__device__ __align__(256) unsigned char g_w2s[103 * 16384];   // all layers' fp16 w2T chunks [64x256B]
__device__ float g_fa[NN * 64];
__device__ float g_fb[NN * 64];
__device__ float g_acc[NN * 64];
__device__ float g_y[NN * 64];        // x @ b2 per node
__device__ float g_sums[NG * 64];
__device__ float g_cnt[NG];
__device__ int g_src[NE], g_dst[NE], g_batch[NN], g_is64;

__device__ __forceinline__ float eluf(float v) { return v > 0.f ? v : expm1f(v); }
__device__ __forceinline__ uint32_t s2u(const void* p) {
    uint32_t a;
    asm("{ .reg .u64 t; cvta.to.shared.u64 t, %1; cvt.u32.u64 %0, t; }" : "=r"(a) : "l"(p));
    return a;
}
__device__ __forceinline__ void cp16(uint32_t s, const void* g) {
    asm volatile("cp.async.cg.shared.global [%0], [%1], 16;" :: "r"(s), "l"(g));
}
__device__ __forceinline__ void cp_commit() { asm volatile("cp.async.commit_group;" ::: "memory"); }
template<int N> __device__ __forceinline__ void cp_wait() { asm volatile("cp.async.wait_group %0;" :: "n"(N) : "memory"); }
__device__ __forceinline__ void ldsm4(uint32_t* r, uint32_t a) {
    asm volatile("ldmatrix.sync.aligned.m8n8.x4.shared.b16 {%0,%1,%2,%3}, [%4];"
                 : "=r"(r[0]), "=r"(r[1]), "=r"(r[2]), "=r"(r[3]) : "r"(a));
}
__device__ __forceinline__ void mma16816(float* d, const uint32_t* a, uint32_t b0, uint32_t b1) {
    asm volatile("mma.sync.aligned.m16n8k16.row.col.f32.f16.f16.f32 "
                 "{%0,%1,%2,%3}, {%4,%5,%6,%7}, {%8,%9}, {%0,%1,%2,%3};"
                 : "+f"(d[0]), "+f"(d[1]), "+f"(d[2]), "+f"(d[3])
                 : "r"(a[0]), "r"(a[1]), "r"(a[2]), "r"(a[3]), "r"(b0), "r"(b1));
}

// ---------------- index dtype detect + convert -----------------------------
__global__ void detect_kernel(const long long* __restrict__ ei) {
    if (blockIdx.x == 0 && threadIdx.x == 0) {
        int is64 = 1;
        for (int i = 0; i < 256; i++) { long long v = ei[i]; if (v < 0 || v >= (long long)NN) { is64 = 0; break; } }
        g_is64 = is64;
    }
}
__global__ void convert_kernel(const void* __restrict__ ei, const void* __restrict__ bat) {
    int t = blockIdx.x * blockDim.x + threadIdx.x;
    const int is64 = g_is64;
    if (t < NE) {
        if (is64) { g_src[t] = (int)((const long long*)ei)[t]; g_dst[t] = (int)((const long long*)ei)[NE + t]; }
        else      { g_src[t] = ((const int*)ei)[t];            g_dst[t] = ((const int*)ei)[NE + t]; }
    }
    if (t < NN) g_batch[t] = is64 ? (int)((const long long*)bat)[t] : ((const int*)bat)[t];
}

__global__ void pool_init_kernel() {
    int t = blockIdx.x * blockDim.x + threadIdx.x;
    if (t < NG * 64) g_sums[t] = 0.f;
    if (t < NG) g_cnt[t] = 0.f;
}

// -------- edge MLP for ALL 3 layers -> fp16 A tiles ------------------------
// Block = 256 threads = 8 warps handles 32 edges. Each lane owns one k-pair
// (w1/b1 loaded ONCE into regs, reused across 8 edges) -> ~8x less L1 traffic
// than thread-per-(e,kpair). Stores stay 128B-coalesced (lane = contiguous k).
__global__ void __launch_bounds__(256)
edge_hA3_kernel(const float* __restrict__ ea,
                const float* __restrict__ w1a, const float* __restrict__ b1a,
                const float* __restrict__ w1b, const float* __restrict__ b1b,
                const float* __restrict__ w1c, const float* __restrict__ b1c) {
    __shared__ float eas[32][5];
    const int tid = threadIdx.x;
    const int eg = blockIdx.x * 32;
    if (tid < 160) {
        int e = eg + tid / 5;
        eas[tid / 5][tid % 5] = (e < NE) ? ea[(size_t)e * 5 + (tid % 5)] : 0.f;
    }
    __syncthreads();

    const int w = tid >> 5, lane = tid & 31;
    const int k = ((w & 1) * 32 + lane) * 2;       // this thread's k-pair
    const int ebase = (w >> 1) * 8;                // 8 edges per warp-pair

    const float* w1s[3] = { w1a, w1b, w1c };
    const float* b1s[3] = { b1a, b1b, b1c };
    float wv[3][10], bv[3][2];
#pragma unroll
    for (int L = 0; L < 3; L++) {
#pragma unroll
        for (int d = 0; d < 5; d++) {
            wv[L][2 * d]     = w1s[L][d * HID + k];
            wv[L][2 * d + 1] = w1s[L][d * HID + k + 1];
        }
        bv[L][0] = b1s[L][k];
        bv[L][1] = b1s[L][k + 1];
    }

#pragma unroll
    for (int j = 0; j < 8; j++) {
        const int e = eg + ebase + j;
        if (e >= NE) break;
        const float a0 = eas[ebase + j][0], a1 = eas[ebase + j][1], a2 = eas[ebase + j][2];
        const float a3 = eas[ebase + j][3], a4 = eas[ebase + j][4];
        const int tile = e >> 7, row = e & 127;
        unsigned char* base = g_hA + (size_t)tile * 32768 + row * 256 + k * 2;
#pragma unroll
        for (int L = 0; L < 3; L++) {
            float s0 = bv[L][0], s1 = bv[L][1];
            s0 = fmaf(a0, wv[L][0], s0); s1 = fmaf(a0, wv[L][1], s1);
            s0 = fmaf(a1, wv[L][2], s0); s1 = fmaf(a1, wv[L][3], s1);
            s0 = fmaf(a2, wv[L][4], s0); s1 = fmaf(a2, wv[L][5], s1);
            s0 = fmaf(a3, wv[L][6], s0); s1 = fmaf(a3, wv[L][7], s1);
            s0 = fmaf(a4, wv[L][8], s0); s1 = fmaf(a4, wv[L][9], s1);
            s0 = fmaxf(s0, 0.f); s1 = fmaxf(s1, 0.f);
            __half h0 = __float2half(s0), h1 = __float2half(s1);
            *(uint32_t*)(base + L * HA_STRIDE) =
                ((uint32_t)__half_as_ushort(h1) << 16) | __half_as_ushort(h0);
        }
    }
}

// -------- w2 -> fp16 B chunk tiles at a given chunk base -------------------
template<int M_IN, int M_OUT, int NC, int CBASE>
__global__ void w2prep_kernel(const float* __restrict__ w2) {
    int t = blockIdx.x * blockDim.x + threadIdx.x;
    if (t >= NC * 8192) return;
    int c = t >> 13, rem = t & 8191, r = rem >> 7, k = rem & 127;
    int n = c * 64 + r;
    float v = (n < M_IN * M_OUT) ? w2[k * (M_IN * M_OUT) + n] : 0.f;
    *(__half*)(g_w2s + (size_t)(CBASE + c) * 16384 + r * 256 + k * 2) = __float2half(v);
}

// -------- acc = x @ root + bias;  g_y = x @ b2  ----------------------------
template<int M_IN, int M_OUT>
__global__ void rootxb2_kernel(const float* __restrict__ x, const float* __restrict__ root,
                               const float* __restrict__ bias, const float* __restrict__ b2,
                               float* __restrict__ acc) {
    int t = blockIdx.x * blockDim.x + threadIdx.x;
    if (t >= NN * M_OUT) return;
    int n = t / M_OUT, o = t - n * M_OUT;
    const float* xr = x + n * M_IN;
    float s = bias[o], y = 0.f;
#pragma unroll
    for (int i = 0; i < M_IN; i++) {
        float xv = xr[i];
        s = fmaf(xv, root[i * M_OUT + o], s);
        y = fmaf(xv, b2[i * M_OUT + o], y);
    }
    acc[t] = s;
    g_y[t] = y;
}

__global__ void elu_kernel(const float* __restrict__ acc, float* __restrict__ xo, int n) {
    int t = blockIdx.x * blockDim.x + threadIdx.x;
    if (t < n) xo[t] = eluf(acc[t]);
}

__global__ void elu_pool_kernel(const float* __restrict__ acc) {
    int t = blockIdx.x * blockDim.x + threadIdx.x;
    if (t >= NN * 64) return;
    int n = t >> 6, o = t & 63;
    float v = eluf(acc[t]);
    int g = g_batch[n];
    atomicAdd(&g_sums[g * 64 + o], v);
    if (o == 0) atomicAdd(&g_cnt[g], 1.f);
}

// -------- layer-1 message GEMM (unsplit, M_OUT=32) -------------------------
__device__ __forceinline__ void copyB64(int cabs, uint32_t dst, int tid) {
    const unsigned char* gb = g_w2s + (size_t)cabs * 16384;
    for (int idx = tid; idx < 1024; idx += 256) {
        int r = idx >> 4, s = idx & 15;
        cp16(dst + r * 272 + s * 16, gb + r * 256 + s * 16);
    }
}

template<int M_IN, int M_OUT, int NC, int CBASE>
__global__ void __launch_bounds__(256, 2)
msg_mma_kernel(const float* __restrict__ xin, float* __restrict__ acc,
               const unsigned char* __restrict__ hA) {
    extern __shared__ char smem[];
    const uint32_t sb = s2u(smem);
    const int tid = threadIdx.x, wid = tid >> 5, lane = tid & 31;
    const int tile = blockIdx.x;

    {
        const unsigned char* ga = hA + (size_t)tile * 32768;
        for (int idx = tid; idx < 2048; idx += 256) {
            int r = (idx >> 4) & 127, s = idx & 15;
            cp16(sb + r * 272 + s * 16, ga + r * 256 + s * 16);
        }
        copyB64(CBASE, sb + SM_B, tid);
        cp_commit();
        if (NC > 1) { copyB64(CBASE + 1, sb + SM_B + SM_BUF, tid); cp_commit(); }
    }

    const int m0 = wid * 16;
    const int r0 = lane >> 2;
    const int e0 = tile * 128 + m0 + r0;
    const int e1 = e0 + 8;
    int src0 = 0, dst0 = -1, src1 = 0, dst1 = -1;
    if (e0 < NE) { src0 = g_src[e0]; dst0 = g_dst[e0]; }
    if (e1 < NE) { src1 = g_src[e1]; dst1 = g_dst[e1]; }

    const uint32_t lrow = (lane & 15);
    const uint32_t kh16 = (lane >> 4) * 16;

    float av[8][4];
#pragma unroll
    for (int nb = 0; nb < 8; nb++)
#pragma unroll
        for (int q = 0; q < 4; q++) av[nb][q] = 0.f;

    for (int c = 0; c < NC; c++) {
        if (c + 1 == NC) cp_wait<0>(); else cp_wait<1>();
        __syncthreads();

        const uint32_t Bb = sb + SM_B + (uint32_t)(c & 1) * SM_BUF;
        float d[8][4];
#pragma unroll
        for (int nb = 0; nb < 8; nb++)
#pragma unroll
            for (int q = 0; q < 4; q++) d[nb][q] = 0.f;

#pragma unroll
        for (int ks = 0; ks < 8; ks++) {
            uint32_t a[4];
            ldsm4(a, sb + (m0 + lrow) * 272 + ks * 32 + kh16);
#pragma unroll
            for (int nb2 = 0; nb2 < 4; nb2++) {
                uint32_t b[4];
                ldsm4(b, Bb + (nb2 * 16 + lrow) * 272 + ks * 32 + kh16);
                mma16816(d[2 * nb2],     a, b[0], b[2]);
                mma16816(d[2 * nb2 + 1], a, b[1], b[3]);
            }
        }

        const int i0 = min(2 * c, M_IN - 1), i1 = min(2 * c + 1, M_IN - 1);
        const float x00 = xin[(size_t)src0 * M_IN + i0];
        const float x01 = xin[(size_t)src0 * M_IN + i1];
        const float x10 = xin[(size_t)src1 * M_IN + i0];
        const float x11 = xin[(size_t)src1 * M_IN + i1];
#pragma unroll
        for (int nb = 0; nb < 8; nb++) {
            const float xsa = (nb < 4) ? x00 : x01;
            const float xsb = (nb < 4) ? x10 : x11;
            av[nb][0] = fmaf(xsa, d[nb][0], av[nb][0]);
            av[nb][1] = fmaf(xsa, d[nb][1], av[nb][1]);
            av[nb][2] = fmaf(xsb, d[nb][2], av[nb][2]);
            av[nb][3] = fmaf(xsb, d[nb][3], av[nb][3]);
        }

        __syncthreads();
        if (c + 2 < NC) { copyB64(CBASE + c + 2, sb + SM_B + (uint32_t)(c & 1) * SM_BUF, tid); cp_commit(); }
    }

    const int oc = (lane & 3) * 2;
#pragma unroll
    for (int nb = 0; nb < 4; nb++) {
        const int o = nb * 8 + oc;
        if (dst0 >= 0) {
            atomicAdd(acc + (size_t)dst0 * 32 + o,     av[nb][0] + av[nb + 4][0] + g_y[(size_t)src0 * 32 + o]);
            atomicAdd(acc + (size_t)dst0 * 32 + o + 1, av[nb][1] + av[nb + 4][1] + g_y[(size_t)src0 * 32 + o + 1]);
        }
        if (dst1 >= 0) {
            atomicAdd(acc + (size_t)dst1 * 32 + o,     av[nb][2] + av[nb + 4][2] + g_y[(size_t)src1 * 32 + o]);
            atomicAdd(acc + (size_t)dst1 * 32 + o + 1, av[nb][3] + av[nb + 4][3] + g_y[(size_t)src1 * 32 + o + 1]);
        }
    }
}

// -------- o-split message GEMM for M_OUT=64 layers -------------------------
// Each chunk's 64 B-rows are o in [0,64) for i=c; split s takes rows
// [32s, 32s+32) -> the two CTAs produce DISJOINT outputs: no extra atomics,
// x@b2 split naturally, B halves already contiguous in g_w2s. 2x grid fills
// the wave tail; smem 52KB -> 3 CTAs/SM (444 slots).
template<int M_IN, int CBASE>
__global__ void __launch_bounds__(256, 3)
msg_mma_o2_kernel(const float* __restrict__ xin, float* __restrict__ acc,
                  const unsigned char* __restrict__ hA) {
    constexpr int NC = M_IN;
    extern __shared__ char smem[];
    const uint32_t sb = s2u(smem);
    const int tid = threadIdx.x, wid = tid >> 5, lane = tid & 31;
    const int tile = blockIdx.x >> 1, sp = blockIdx.x & 1;

    // prologue: A + B0 as group0; B1 as group1
    {
        const unsigned char* ga = hA + (size_t)tile * 32768;
        for (int idx = tid; idx < 2048; idx += 256) {
            int r = (idx >> 4) & 127, s = idx & 15;
            cp16(sb + r * 272 + s * 16, ga + r * 256 + s * 16);
        }
        const unsigned char* gb0 = g_w2s + (size_t)CBASE * 16384 + sp * 8192;
        for (int idx = tid; idx < 512; idx += 256) {
            int r = idx >> 4, s = idx & 15;
            cp16(sb + SM_B + r * 272 + s * 16, gb0 + r * 256 + s * 16);
        }
        cp_commit();
        const unsigned char* gb1 = g_w2s + (size_t)(CBASE + 1) * 16384 + sp * 8192;
        for (int idx = tid; idx < 512; idx += 256) {
            int r = idx >> 4, s = idx & 15;
            cp16(sb + SM_B + SM_BUF2 + r * 272 + s * 16, gb1 + r * 256 + s * 16);
        }
        cp_commit();
    }

    const int m0 = wid * 16;
    const int r0 = lane >> 2;
    const int e0 = tile * 128 + m0 + r0;
    const int e1 = e0 + 8;
    int src0 = 0, dst0 = -1, src1 = 0, dst1 = -1;
    if (e0 < NE) { src0 = g_src[e0]; dst0 = g_dst[e0]; }
    if (e1 < NE) { src1 = g_src[e1]; dst1 = g_dst[e1]; }

    const uint32_t lrow = (lane & 15);
    const uint32_t kh16 = (lane >> 4) * 16;

    float av[4][4];
#pragma unroll
    for (int nb = 0; nb < 4; nb++)
#pragma unroll
        for (int q = 0; q < 4; q++) av[nb][q] = 0.f;

    for (int c = 0; c < NC; c++) {
        if (c + 1 == NC) cp_wait<0>(); else cp_wait<1>();
        __syncthreads();

        const uint32_t Bb = sb + SM_B + (uint32_t)(c & 1) * SM_BUF2;
        float d[4][4];
#pragma unroll
        for (int nb = 0; nb < 4; nb++)
#pragma unroll
            for (int q = 0; q < 4; q++) d[nb][q] = 0.f;

#pragma unroll
        for (int ks = 0; ks < 8; ks++) {
            uint32_t a[4];
            ldsm4(a, sb + (m0 + lrow) * 272 + ks * 32 + kh16);
#pragma unroll
            for (int nb2 = 0; nb2 < 2; nb2++) {
                uint32_t b[4];
                ldsm4(b, Bb + (nb2 * 16 + lrow) * 272 + ks * 32 + kh16);
                mma16816(d[2 * nb2],     a, b[0], b[2]);
                mma16816(d[2 * nb2 + 1], a, b[1], b[3]);
            }
        }

        const float xs0 = xin[(size_t)src0 * M_IN + c];
        const float xs1 = xin[(size_t)src1 * M_IN + c];
#pragma unroll
        for (int nb = 0; nb < 4; nb++) {
            av[nb][0] = fmaf(xs0, d[nb][0], av[nb][0]);
            av[nb][1] = fmaf(xs0, d[nb][1], av[nb][1]);
            av[nb][2] = fmaf(xs1, d[nb][2], av[nb][2]);
            av[nb][3] = fmaf(xs1, d[nb][3], av[nb][3]);
        }

        __syncthreads();
        if (c + 2 < NC) {
            const unsigned char* gb = g_w2s + (size_t)(CBASE + c + 2) * 16384 + sp * 8192;
            uint32_t dst = sb + SM_B + (uint32_t)(c & 1) * SM_BUF2;
            for (int idx = tid; idx < 512; idx += 256) {
                int r = idx >> 4, s = idx & 15;
                cp16(dst + r * 272 + s * 16, gb + r * 256 + s * 16);
            }
            cp_commit();
        }
    }

    // scatter: split sp owns o in [32sp, 32sp+32) -- disjoint, so y added here
    const int oc = (lane & 3) * 2;
#pragma unroll
    for (int nb = 0; nb < 4; nb++) {
        const int o = sp * 32 + nb * 8 + oc;
        if (dst0 >= 0) {
            atomicAdd(acc + (size_t)dst0 * 64 + o,     av[nb][0] + g_y[(size_t)src0 * 64 + o]);
            atomicAdd(acc + (size_t)dst0 * 64 + o + 1, av[nb][1] + g_y[(size_t)src0 * 64 + o + 1]);
        }
        if (dst1 >= 0) {
            atomicAdd(acc + (size_t)dst1 * 64 + o,     av[nb][2] + g_y[(size_t)src1 * 64 + o]);
            atomicAdd(acc + (size_t)dst1 * 64 + o + 1, av[nb][3] + g_y[(size_t)src1 * 64 + o + 1]);
        }
    }
}

// ---------------- final MLP -------------------------------------------------
__global__ void __launch_bounds__(128)
mlp_kernel(const float* __restrict__ f1w, const float* __restrict__ f1b,
           const float* __restrict__ f2w, const float* __restrict__ f2b,
           const float* __restrict__ f3w, const float* __restrict__ f3b,
           float* __restrict__ out) {
    int g = blockIdx.x * blockDim.x + threadIdx.x;
    if (g >= NG) return;
    float inv = 1.f / fmaxf(g_cnt[g], 1.f);
    const float* sr = g_sums + g * 64;
    float h1[32];
#pragma unroll
    for (int j = 0; j < 32; j++) {
        float s = 0.f;
#pragma unroll
        for (int i = 0; i < 64; i++) s = fmaf(sr[i], f1w[i * 32 + j], s);
        h1[j] = eluf(fmaf(s, inv, f1b[j]));
    }
    float h2[16];
#pragma unroll
    for (int j = 0; j < 16; j++) {
        float s = f2b[j];
#pragma unroll
        for (int i = 0; i < 32; i++) s = fmaf(h1[i], f2w[i * 16 + j], s);
        h2[j] = eluf(s);
    }
    float s = f3b[0];
#pragma unroll
    for (int i = 0; i < 16; i++) s = fmaf(h2[i], f3w[i], s);
    out[g] = s;
}

// ---------------- driver ----------------------------------------------------
extern "C" void kernel_launch(void* const* d_in, const int* in_sizes, int n_in,
                              void* d_out, int out_size) {
    const float* x   = (const float*)d_in[0];
    const void*  ei  = d_in[1];
    const float* ea  = (const float*)d_in[2];
    const void*  bat = d_in[3];
    const float* W[24];
    for (int i = 0; i < 24; i++) W[i] = (const float*)d_in[4 + i];
    float* out = (float*)d_out;

    float *fa, *fb, *acc;
    unsigned char* hA;
    cudaGetSymbolAddress((void**)&fa, g_fa);
    cudaGetSymbolAddress((void**)&fb, g_fb);
    cudaGetSymbolAddress((void**)&acc, g_acc);
    cudaGetSymbolAddress((void**)&hA, g_hA);

    cudaFuncSetAttribute(msg_mma_kernel<13, 32, 7, 0>, cudaFuncAttributeMaxDynamicSharedMemorySize, SMEM_BYTES);
    cudaFuncSetAttribute(msg_mma_o2_kernel<32, 7>,     cudaFuncAttributeMaxDynamicSharedMemorySize, SMEM2_BYTES);
    cudaFuncSetAttribute(msg_mma_o2_kernel<64, 39>,    cudaFuncAttributeMaxDynamicSharedMemorySize, SMEM2_BYTES);

    detect_kernel<<<1, 32>>>((const long long*)ei);
    convert_kernel<<<(NE + 255) / 256, 256>>>(ei, bat);
    pool_init_kernel<<<(NG * 64 + 255) / 256, 256>>>();

    // all prep up front
    edge_hA3_kernel<<<(NE + 31) / 32, 256>>>(ea, W[0], W[1], W[6], W[7], W[12], W[13]);
    w2prep_kernel<13, 32, 7, 0>  <<<(7 * 8192 + 255) / 256, 256>>>(W[2]);
    w2prep_kernel<32, 64, 32, 7> <<<(32 * 8192 + 255) / 256, 256>>>(W[8]);
    w2prep_kernel<64, 64, 64, 39><<<(64 * 8192 + 255) / 256, 256>>>(W[14]);

    // layer 1: 13 -> 32
    rootxb2_kernel<13, 32><<<(NN * 32 + 255) / 256, 256>>>(x, W[4], W[5], W[3], acc);
    msg_mma_kernel<13, 32, 7, 0><<<NTILES, 256, SMEM_BYTES>>>(x, acc, hA);
    elu_kernel<<<(NN * 32 + 255) / 256, 256>>>(acc, fa, NN * 32);

    // layer 2: 32 -> 64 (o-split x2)
    rootxb2_kernel<32, 64><<<(NN * 64 + 255) / 256, 256>>>(fa, W[10], W[11], W[9], acc);
    msg_mma_o2_kernel<32, 7><<<NTILES * 2, 256, SMEM2_BYTES>>>(fa, acc, hA + HA_STRIDE);
    elu_kernel<<<(NN * 64 + 255) / 256, 256>>>(acc, fb, NN * 64);

    // layer 3: 64 -> 64 (o-split x2; elu fused with pooling)
    rootxb2_kernel<64, 64><<<(NN * 64 + 255) / 256, 256>>>(fb, W[16], W[17], W[15], acc);
    msg_mma_o2_kernel<64, 39><<<NTILES * 2, 256, SMEM2_BYTES>>>(fb, acc, hA + 2 * HA_STRIDE);
    elu_pool_kernel<<<(NN * 64 + 255) / 256, 256>>>(acc);

    // head
    mlp_kernel<<<(NG + 127) / 128, 128>>>(W[18], W[19], W[20], W[21], W[22], W[23], out);
}

// round 10
// speedup vs baseline: 1.1221x; 1.1221x over previous
#include <cuda_runtime.h>
#include <cuda_fp16.h>
#include <math.h>
#include <stdint.h>

#define NE 50000
#define NN 25000
#define NG 1024
#define HID 128
#define NTILES 391
#define HA_STRIDE ((size_t)NTILES * 32768)

// msg smem: A [128x272B] | B buf0 [64x272B] | B buf1
#define SM_B      34816
#define SM_BUF    17408
#define SMEM_BYTES 69632

__device__ __align__(256) unsigned char g_hA[3 * HA_STRIDE];  // per-layer, per-tile fp16 h [128x256B]
__device__ __align__(256) unsigned char g_w2s[103 * 16384];   // all layers' fp16 w2T chunks [64x256B]
__device__ float g_fa[NN * 64];
__device__ float g_fb[NN * 64];
__device__ float g_acc[NN * 64];
__device__ float g_acc2[NN * 64];
__device__ float g_y[NN * 64];        // x @ b2 per node
__device__ float g_sums[NG * 64];
__device__ float g_cnt[NG];
__device__ int g_src[NE], g_dst[NE], g_batch[NN], g_is64;

__device__ __forceinline__ float eluf(float v) { return v > 0.f ? v : expm1f(v); }
__device__ __forceinline__ uint32_t s2u(const void* p) {
    uint32_t a;
    asm("{ .reg .u64 t; cvta.to.shared.u64 t, %1; cvt.u32.u64 %0, t; }" : "=r"(a) : "l"(p));
    return a;
}
__device__ __forceinline__ void cp16(uint32_t s, const void* g) {
    asm volatile("cp.async.cg.shared.global [%0], [%1], 16;" :: "r"(s), "l"(g));
}
__device__ __forceinline__ void cp_commit() { asm volatile("cp.async.commit_group;" ::: "memory"); }
template<int N> __device__ __forceinline__ void cp_wait() { asm volatile("cp.async.wait_group %0;" :: "n"(N) : "memory"); }
__device__ __forceinline__ void ldsm4(uint32_t* r, uint32_t a) {
    asm volatile("ldmatrix.sync.aligned.m8n8.x4.shared.b16 {%0,%1,%2,%3}, [%4];"
                 : "=r"(r[0]), "=r"(r[1]), "=r"(r[2]), "=r"(r[3]) : "r"(a));
}
__device__ __forceinline__ void mma16816(float* d, const uint32_t* a, uint32_t b0, uint32_t b1) {
    asm volatile("mma.sync.aligned.m16n8k16.row.col.f32.f16.f16.f32 "
                 "{%0,%1,%2,%3}, {%4,%5,%6,%7}, {%8,%9}, {%0,%1,%2,%3};"
                 : "+f"(d[0]), "+f"(d[1]), "+f"(d[2]), "+f"(d[3])
                 : "r"(a[0]), "r"(a[1]), "r"(a[2]), "r"(a[3]), "r"(b0), "r"(b1));
}

// ---------------- index dtype detect + convert -----------------------------
__global__ void detect_kernel(const long long* __restrict__ ei) {
    if (blockIdx.x == 0 && threadIdx.x == 0) {
        int is64 = 1;
        for (int i = 0; i < 256; i++) { long long v = ei[i]; if (v < 0 || v >= (long long)NN) { is64 = 0; break; } }
        g_is64 = is64;
    }
}
__global__ void convert_kernel(const void* __restrict__ ei, const void* __restrict__ bat) {
    int t = blockIdx.x * blockDim.x + threadIdx.x;
    const int is64 = g_is64;
    if (t < NE) {
        if (is64) { g_src[t] = (int)((const long long*)ei)[t]; g_dst[t] = (int)((const long long*)ei)[NE + t]; }
        else      { g_src[t] = ((const int*)ei)[t];            g_dst[t] = ((const int*)ei)[NE + t]; }
    }
    if (t < NN) g_batch[t] = is64 ? (int)((const long long*)bat)[t] : ((const int*)bat)[t];
    if (t < NG * 64) g_sums[t] = 0.f;
    if (t < NG) g_cnt[t] = 0.f;
}

// -------- edge MLP for ALL 3 layers -> fp16 A tiles (warp-structured) ------
__global__ void __launch_bounds__(256)
edge_hA3_kernel(const float* __restrict__ ea,
                const float* __restrict__ w1a, const float* __restrict__ b1a,
                const float* __restrict__ w1b, const float* __restrict__ b1b,
                const float* __restrict__ w1c, const float* __restrict__ b1c) {
    __shared__ float eas[32][5];
    const int tid = threadIdx.x;
    const int eg = blockIdx.x * 32;
    if (tid < 160) {
        int e = eg + tid / 5;
        eas[tid / 5][tid % 5] = (e < NE) ? ea[(size_t)e * 5 + (tid % 5)] : 0.f;
    }
    __syncthreads();

    const int w = tid >> 5, lane = tid & 31;
    const int k = ((w & 1) * 32 + lane) * 2;
    const int ebase = (w >> 1) * 8;

    const float* w1s[3] = { w1a, w1b, w1c };
    const float* b1s[3] = { b1a, b1b, b1c };
    float wv[3][10], bv[3][2];
#pragma unroll
    for (int L = 0; L < 3; L++) {
#pragma unroll
        for (int d = 0; d < 5; d++) {
            wv[L][2 * d]     = w1s[L][d * HID + k];
            wv[L][2 * d + 1] = w1s[L][d * HID + k + 1];
        }
        bv[L][0] = b1s[L][k];
        bv[L][1] = b1s[L][k + 1];
    }

#pragma unroll
    for (int j = 0; j < 8; j++) {
        const int e = eg + ebase + j;
        if (e >= NE) break;
        const float a0 = eas[ebase + j][0], a1 = eas[ebase + j][1], a2 = eas[ebase + j][2];
        const float a3 = eas[ebase + j][3], a4 = eas[ebase + j][4];
        const int tile = e >> 7, row = e & 127;
        unsigned char* base = g_hA + (size_t)tile * 32768 + row * 256 + k * 2;
#pragma unroll
        for (int L = 0; L < 3; L++) {
            float s0 = bv[L][0], s1 = bv[L][1];
            s0 = fmaf(a0, wv[L][0], s0); s1 = fmaf(a0, wv[L][1], s1);
            s0 = fmaf(a1, wv[L][2], s0); s1 = fmaf(a1, wv[L][3], s1);
            s0 = fmaf(a2, wv[L][4], s0); s1 = fmaf(a2, wv[L][5], s1);
            s0 = fmaf(a3, wv[L][6], s0); s1 = fmaf(a3, wv[L][7], s1);
            s0 = fmaf(a4, wv[L][8], s0); s1 = fmaf(a4, wv[L][9], s1);
            s0 = fmaxf(s0, 0.f); s1 = fmaxf(s1, 0.f);
            __half h0 = __float2half(s0), h1 = __float2half(s1);
            *(uint32_t*)(base + L * HA_STRIDE) =
                ((uint32_t)__half_as_ushort(h1) << 16) | __half_as_ushort(h0);
        }
    }
}

// -------- all 3 layers' w2 -> fp16 B chunk tiles (one launch) --------------
__global__ void w2prep_all_kernel(const float* __restrict__ w2a,
                                  const float* __restrict__ w2b,
                                  const float* __restrict__ w2c) {
    int t = blockIdx.x * blockDim.x + threadIdx.x;
    if (t >= 103 * 8192) return;
    int c = t >> 13, rem = t & 8191, r = rem >> 7, k = rem & 127;
    const float* w2; int cb, sz;
    if (c < 7)       { w2 = w2a; cb = 0;  sz = 13 * 32; }
    else if (c < 39) { w2 = w2b; cb = 7;  sz = 32 * 64; }
    else             { w2 = w2c; cb = 39; sz = 64 * 64; }
    int n = (c - cb) * 64 + r;
    float v = (n < sz) ? w2[k * sz + n] : 0.f;
    *(__half*)(g_w2s + (size_t)c * 16384 + r * 256 + k * 2) = __float2half(v);
}

// -------- layer-1 entry: acc = x @ root + bias; g_y = x @ b2 ---------------
template<int M_IN, int M_OUT>
__global__ void rootxb2_kernel(const float* __restrict__ x, const float* __restrict__ root,
                               const float* __restrict__ bias, const float* __restrict__ b2,
                               float* __restrict__ acc) {
    int t = blockIdx.x * blockDim.x + threadIdx.x;
    if (t >= NN * M_OUT) return;
    int n = t / M_OUT, o = t - n * M_OUT;
    const float* xr = x + n * M_IN;
    float s = bias[o], y = 0.f;
#pragma unroll
    for (int i = 0; i < M_IN; i++) {
        float xv = xr[i];
        s = fmaf(xv, root[i * M_OUT + o], s);
        y = fmaf(xv, b2[i * M_OUT + o], y);
    }
    acc[t] = s;
    g_y[t] = y;
}

// -------- layer transition: f = elu(acc_in); acc_out = f@root+bias; y = f@b2
// Block = 256 threads = 4 nodes x 64 outputs; f staged in smem (one elu each),
// then both dot products read smem (warp-broadcast). acc_in / acc_out are
// DIFFERENT buffers (avoids cross-block races on the 32->64 width change).
template<int MI>
__global__ void __launch_bounds__(256)
trans_kernel(const float* __restrict__ acc_in, float* __restrict__ fout,
             const float* __restrict__ root, const float* __restrict__ bias,
             const float* __restrict__ b2, float* __restrict__ acc_out) {
    __shared__ float f[4][MI];
    const int tid = threadIdx.x;
    const int n0 = blockIdx.x * 4;
    if (tid < 4 * MI) {
        int n = tid / MI, i = tid - n * MI;
        float v = eluf(acc_in[(size_t)(n0 + n) * MI + i]);
        f[n][i] = v;
        fout[(size_t)(n0 + n) * MI + i] = v;
    }
    __syncthreads();
    const int n = tid >> 6, o = tid & 63;
    float s = bias[o], y = 0.f;
#pragma unroll
    for (int i = 0; i < MI; i++) {
        float fv = f[n][i];
        s = fmaf(fv, root[i * 64 + o], s);
        y = fmaf(fv, b2[i * 64 + o], y);
    }
    acc_out[(size_t)(n0 + n) * 64 + o] = s;
    g_y[(size_t)(n0 + n) * 64 + o] = y;
}

// -------- layer-3 elu fused with graph pooling -----------------------------
__global__ void elu_pool_kernel(const float* __restrict__ acc) {
    int t = blockIdx.x * blockDim.x + threadIdx.x;
    if (t >= NN * 64) return;
    int n = t >> 6, o = t & 63;
    float v = eluf(acc[t]);
    int g = g_batch[n];
    atomicAdd(&g_sums[g * 64 + o], v);
    if (o == 0) atomicAdd(&g_cnt[g], 1.f);
}

// -------- message GEMM (fp16 mma, R7 config) + contract + scatter ----------
__device__ __forceinline__ void copyB(int cabs, uint32_t dst, int tid) {
    const unsigned char* gb = g_w2s + (size_t)cabs * 16384;
    for (int idx = tid; idx < 1024; idx += 256) {
        int r = idx >> 4, s = idx & 15;
        cp16(dst + r * 272 + s * 16, gb + r * 256 + s * 16);
    }
}

template<int M_IN, int M_OUT, int NC, int CBASE>
__global__ void __launch_bounds__(256, 2)
msg_mma_kernel(const float* __restrict__ xin, float* __restrict__ acc,
               const unsigned char* __restrict__ hA) {
    extern __shared__ char smem[];
    const uint32_t sb = s2u(smem);
    const int tid = threadIdx.x, wid = tid >> 5, lane = tid & 31;
    const int tile = blockIdx.x;

    {
        const unsigned char* ga = hA + (size_t)tile * 32768;
        for (int idx = tid; idx < 2048; idx += 256) {
            int r = (idx >> 4) & 127, s = idx & 15;
            cp16(sb + r * 272 + s * 16, ga + r * 256 + s * 16);
        }
        copyB(CBASE, sb + SM_B, tid);
        cp_commit();
        if (NC > 1) { copyB(CBASE + 1, sb + SM_B + SM_BUF, tid); cp_commit(); }
    }

    const int m0 = wid * 16;
    const int r0 = lane >> 2;
    const int e0 = tile * 128 + m0 + r0;
    const int e1 = e0 + 8;
    int src0 = 0, dst0 = -1, src1 = 0, dst1 = -1;
    if (e0 < NE) { src0 = g_src[e0]; dst0 = g_dst[e0]; }
    if (e1 < NE) { src1 = g_src[e1]; dst1 = g_dst[e1]; }

    const uint32_t lrow = (lane & 15);
    const uint32_t kh16 = (lane >> 4) * 16;

    float av[8][4];
#pragma unroll
    for (int nb = 0; nb < 8; nb++)
#pragma unroll
        for (int q = 0; q < 4; q++) av[nb][q] = 0.f;

    for (int c = 0; c < NC; c++) {
        if (c + 1 == NC) cp_wait<0>(); else cp_wait<1>();
        __syncthreads();

        const uint32_t Bb = sb + SM_B + (uint32_t)(c & 1) * SM_BUF;
        float d[8][4];
#pragma unroll
        for (int nb = 0; nb < 8; nb++)
#pragma unroll
            for (int q = 0; q < 4; q++) d[nb][q] = 0.f;

#pragma unroll
        for (int ks = 0; ks < 8; ks++) {
            uint32_t a[4];
            ldsm4(a, sb + (m0 + lrow) * 272 + ks * 32 + kh16);
#pragma unroll
            for (int nb2 = 0; nb2 < 4; nb2++) {
                uint32_t b[4];
                ldsm4(b, Bb + (nb2 * 16 + lrow) * 272 + ks * 32 + kh16);
                mma16816(d[2 * nb2],     a, b[0], b[2]);
                mma16816(d[2 * nb2 + 1], a, b[1], b[3]);
            }
        }

        if constexpr (M_OUT == 64) {
            const float xs0 = xin[(size_t)src0 * M_IN + c];
            const float xs1 = xin[(size_t)src1 * M_IN + c];
#pragma unroll
            for (int nb = 0; nb < 8; nb++) {
                av[nb][0] = fmaf(xs0, d[nb][0], av[nb][0]);
                av[nb][1] = fmaf(xs0, d[nb][1], av[nb][1]);
                av[nb][2] = fmaf(xs1, d[nb][2], av[nb][2]);
                av[nb][3] = fmaf(xs1, d[nb][3], av[nb][3]);
            }
        } else {
            const int i0 = min(2 * c, M_IN - 1), i1 = min(2 * c + 1, M_IN - 1);
            const float x00 = xin[(size_t)src0 * M_IN + i0];
            const float x01 = xin[(size_t)src0 * M_IN + i1];
            const float x10 = xin[(size_t)src1 * M_IN + i0];
            const float x11 = xin[(size_t)src1 * M_IN + i1];
#pragma unroll
            for (int nb = 0; nb < 8; nb++) {
                const float xsa = (nb < 4) ? x00 : x01;
                const float xsb = (nb < 4) ? x10 : x11;
                av[nb][0] = fmaf(xsa, d[nb][0], av[nb][0]);
                av[nb][1] = fmaf(xsa, d[nb][1], av[nb][1]);
                av[nb][2] = fmaf(xsb, d[nb][2], av[nb][2]);
                av[nb][3] = fmaf(xsb, d[nb][3], av[nb][3]);
            }
        }

        __syncthreads();
        if (c + 2 < NC) { copyB(CBASE + c + 2, sb + SM_B + (uint32_t)(c & 1) * SM_BUF, tid); cp_commit(); }
    }

    const int oc = (lane & 3) * 2;
    if constexpr (M_OUT == 64) {
#pragma unroll
        for (int nb = 0; nb < 8; nb++) {
            const int o = nb * 8 + oc;
            if (dst0 >= 0) {
                atomicAdd(acc + (size_t)dst0 * 64 + o,     av[nb][0] + g_y[(size_t)src0 * 64 + o]);
                atomicAdd(acc + (size_t)dst0 * 64 + o + 1, av[nb][1] + g_y[(size_t)src0 * 64 + o + 1]);
            }
            if (dst1 >= 0) {
                atomicAdd(acc + (size_t)dst1 * 64 + o,     av[nb][2] + g_y[(size_t)src1 * 64 + o]);
                atomicAdd(acc + (size_t)dst1 * 64 + o + 1, av[nb][3] + g_y[(size_t)src1 * 64 + o + 1]);
            }
        }
    } else {
#pragma unroll
        for (int nb = 0; nb < 4; nb++) {
            const int o = nb * 8 + oc;
            if (dst0 >= 0) {
                atomicAdd(acc + (size_t)dst0 * 32 + o,     av[nb][0] + av[nb + 4][0] + g_y[(size_t)src0 * 32 + o]);
                atomicAdd(acc + (size_t)dst0 * 32 + o + 1, av[nb][1] + av[nb + 4][1] + g_y[(size_t)src0 * 32 + o + 1]);
            }
            if (dst1 >= 0) {
                atomicAdd(acc + (size_t)dst1 * 32 + o,     av[nb][2] + av[nb + 4][2] + g_y[(size_t)src1 * 32 + o]);
                atomicAdd(acc + (size_t)dst1 * 32 + o + 1, av[nb][3] + av[nb + 4][3] + g_y[(size_t)src1 * 32 + o + 1]);
            }
        }
    }
}

// ---------------- final MLP -------------------------------------------------
__global__ void __launch_bounds__(128)
mlp_kernel(const float* __restrict__ f1w, const float* __restrict__ f1b,
           const float* __restrict__ f2w, const float* __restrict__ f2b,
           const float* __restrict__ f3w, const float* __restrict__ f3b,
           float* __restrict__ out) {
    int g = blockIdx.x * blockDim.x + threadIdx.x;
    if (g >= NG) return;
    float inv = 1.f / fmaxf(g_cnt[g], 1.f);
    const float* sr = g_sums + g * 64;
    float h1[32];
#pragma unroll
    for (int j = 0; j < 32; j++) {
        float s = 0.f;
#pragma unroll
        for (int i = 0; i < 64; i++) s = fmaf(sr[i], f1w[i * 32 + j], s);
        h1[j] = eluf(fmaf(s, inv, f1b[j]));
    }
    float h2[16];
#pragma unroll
    for (int j = 0; j < 16; j++) {
        float s = f2b[j];
#pragma unroll
        for (int i = 0; i < 32; i++) s = fmaf(h1[i], f2w[i * 16 + j], s);
        h2[j] = eluf(s);
    }
    float s = f3b[0];
#pragma unroll
    for (int i = 0; i < 16; i++) s = fmaf(h2[i], f3w[i], s);
    out[g] = s;
}

// ---------------- driver ----------------------------------------------------
extern "C" void kernel_launch(void* const* d_in, const int* in_sizes, int n_in,
                              void* d_out, int out_size) {
    const float* x   = (const float*)d_in[0];
    const void*  ei  = d_in[1];
    const float* ea  = (const float*)d_in[2];
    const void*  bat = d_in[3];
    const float* W[24];
    for (int i = 0; i < 24; i++) W[i] = (const float*)d_in[4 + i];
    float* out = (float*)d_out;

    float *fa, *fb, *acc, *acc2;
    unsigned char* hA;
    cudaGetSymbolAddress((void**)&fa, g_fa);
    cudaGetSymbolAddress((void**)&fb, g_fb);
    cudaGetSymbolAddress((void**)&acc, g_acc);
    cudaGetSymbolAddress((void**)&acc2, g_acc2);
    cudaGetSymbolAddress((void**)&hA, g_hA);

    cudaFuncSetAttribute(msg_mma_kernel<13, 32, 7, 0>,   cudaFuncAttributeMaxDynamicSharedMemorySize, SMEM_BYTES);
    cudaFuncSetAttribute(msg_mma_kernel<32, 64, 32, 7>,  cudaFuncAttributeMaxDynamicSharedMemorySize, SMEM_BYTES);
    cudaFuncSetAttribute(msg_mma_kernel<64, 64, 64, 39>, cudaFuncAttributeMaxDynamicSharedMemorySize, SMEM_BYTES);

    detect_kernel<<<1, 32>>>((const long long*)ei);
    convert_kernel<<<(NG * 64 + 255) / 256, 256>>>(ei, bat);   // also zeroes pooling buffers

    // prep
    edge_hA3_kernel<<<(NE + 31) / 32, 256>>>(ea, W[0], W[1], W[6], W[7], W[12], W[13]);
    w2prep_all_kernel<<<(103 * 8192 + 255) / 256, 256>>>(W[2], W[8], W[14]);

    // layer 1: 13 -> 32
    rootxb2_kernel<13, 32><<<(NN * 32 + 255) / 256, 256>>>(x, W[4], W[5], W[3], acc);
    msg_mma_kernel<13, 32, 7, 0><<<NTILES, 256, SMEM_BYTES>>>(x, acc, hA);

    // transition 1->2: elu(acc[32]) -> fa; acc2 = fa@root2+bias2; y = fa@b2_2
    trans_kernel<32><<<NN / 4, 256>>>(acc, fa, W[10], W[11], W[9], acc2);
    msg_mma_kernel<32, 64, 32, 7><<<NTILES, 256, SMEM_BYTES>>>(fa, acc2, hA + HA_STRIDE);

    // transition 2->3: elu(acc2[64]) -> fb; acc = fb@root3+bias3; y = fb@b2_3
    trans_kernel<64><<<NN / 4, 256>>>(acc2, fb, W[16], W[17], W[15], acc);
    msg_mma_kernel<64, 64, 64, 39><<<NTILES, 256, SMEM_BYTES>>>(fb, acc, hA + 2 * HA_STRIDE);

    // layer-3 elu + pooling, then head
    elu_pool_kernel<<<(NN * 64 + 255) / 256, 256>>>(acc);
    mlp_kernel<<<(NG + 127) / 128, 128>>>(W[18], W[19], W[20], W[21], W[22], W[23], out);
}

// round 11
// speedup vs baseline: 1.1615x; 1.0352x over previous
#include <cuda_runtime.h>
#include <cuda_fp16.h>
#include <math.h>
#include <stdint.h>

#define NE 50000
#define NN 25000
#define NG 1024
#define HID 128
#define NTILES 391

// msg smem (dynamic): A [128x272B] | B buf0 [64x272B] | B buf1
#define SM_B      34816
#define SM_BUF    17408
#define SMEM_BYTES 69632

__device__ __align__(256) unsigned char g_w2s[103 * 16384];   // all layers' fp16 w2T chunks [64x256B]
__device__ float g_fa[NN * 64];
__device__ float g_fb[NN * 64];
__device__ float g_acc[NN * 64];
__device__ float g_acc2[NN * 64];
__device__ float g_y[NN * 64];        // x @ b2 per node
__device__ float g_sums[NG * 64];
__device__ float g_cnt[NG];
__device__ int g_src[NE], g_dst[NE], g_batch[NN], g_is64;

__device__ __forceinline__ float eluf(float v) { return v > 0.f ? v : expm1f(v); }
__device__ __forceinline__ uint32_t s2u(const void* p) {
    uint32_t a;
    asm("{ .reg .u64 t; cvta.to.shared.u64 t, %1; cvt.u32.u64 %0, t; }" : "=r"(a) : "l"(p));
    return a;
}
__device__ __forceinline__ void cp16(uint32_t s, const void* g) {
    asm volatile("cp.async.cg.shared.global [%0], [%1], 16;" :: "r"(s), "l"(g));
}
__device__ __forceinline__ void cp_commit() { asm volatile("cp.async.commit_group;" ::: "memory"); }
template<int N> __device__ __forceinline__ void cp_wait() { asm volatile("cp.async.wait_group %0;" :: "n"(N) : "memory"); }
__device__ __forceinline__ void ldsm4(uint32_t* r, uint32_t a) {
    asm volatile("ldmatrix.sync.aligned.m8n8.x4.shared.b16 {%0,%1,%2,%3}, [%4];"
                 : "=r"(r[0]), "=r"(r[1]), "=r"(r[2]), "=r"(r[3]) : "r"(a));
}
__device__ __forceinline__ void mma16816(float* d, const uint32_t* a, uint32_t b0, uint32_t b1) {
    asm volatile("mma.sync.aligned.m16n8k16.row.col.f32.f16.f16.f32 "
                 "{%0,%1,%2,%3}, {%4,%5,%6,%7}, {%8,%9}, {%0,%1,%2,%3};"
                 : "+f"(d[0]), "+f"(d[1]), "+f"(d[2]), "+f"(d[3])
                 : "r"(a[0]), "r"(a[1]), "r"(a[2]), "r"(a[3]), "r"(b0), "r"(b1));
}

// ---------------- index dtype detect + convert + pool-zero -----------------
__global__ void detect_kernel(const long long* __restrict__ ei) {
    if (blockIdx.x == 0 && threadIdx.x == 0) {
        int is64 = 1;
        for (int i = 0; i < 256; i++) { long long v = ei[i]; if (v < 0 || v >= (long long)NN) { is64 = 0; break; } }
        g_is64 = is64;
    }
}
__global__ void convert_kernel(const void* __restrict__ ei, const void* __restrict__ bat) {
    int t = blockIdx.x * blockDim.x + threadIdx.x;
    const int is64 = g_is64;
    if (t < NE) {
        if (is64) { g_src[t] = (int)((const long long*)ei)[t]; g_dst[t] = (int)((const long long*)ei)[NE + t]; }
        else      { g_src[t] = ((const int*)ei)[t];            g_dst[t] = ((const int*)ei)[NE + t]; }
    }
    if (t < NN) g_batch[t] = is64 ? (int)((const long long*)bat)[t] : ((const int*)bat)[t];
    if (t < NG * 64) g_sums[t] = 0.f;
    if (t < NG) g_cnt[t] = 0.f;
}

// -------- all 3 layers' w2 -> fp16 B chunk tiles (one launch) --------------
__global__ void w2prep_all_kernel(const float* __restrict__ w2a,
                                  const float* __restrict__ w2b,
                                  const float* __restrict__ w2c) {
    int t = blockIdx.x * blockDim.x + threadIdx.x;
    if (t >= 103 * 8192) return;
    int c = t >> 13, rem = t & 8191, r = rem >> 7, k = rem & 127;
    const float* w2; int cb, sz;
    if (c < 7)       { w2 = w2a; cb = 0;  sz = 13 * 32; }
    else if (c < 39) { w2 = w2b; cb = 7;  sz = 32 * 64; }
    else             { w2 = w2c; cb = 39; sz = 64 * 64; }
    int n = (c - cb) * 64 + r;
    float v = (n < sz) ? w2[k * sz + n] : 0.f;
    *(__half*)(g_w2s + (size_t)c * 16384 + r * 256 + k * 2) = __float2half(v);
}

// -------- layer-1 entry: acc = x @ root + bias; g_y = x @ b2 ---------------
template<int M_IN, int M_OUT>
__global__ void rootxb2_kernel(const float* __restrict__ x, const float* __restrict__ root,
                               const float* __restrict__ bias, const float* __restrict__ b2,
                               float* __restrict__ acc) {
    int t = blockIdx.x * blockDim.x + threadIdx.x;
    if (t >= NN * M_OUT) return;
    int n = t / M_OUT, o = t - n * M_OUT;
    const float* xr = x + n * M_IN;
    float s = bias[o], y = 0.f;
#pragma unroll
    for (int i = 0; i < M_IN; i++) {
        float xv = xr[i];
        s = fmaf(xv, root[i * M_OUT + o], s);
        y = fmaf(xv, b2[i * M_OUT + o], y);
    }
    acc[t] = s;
    g_y[t] = y;
}

// -------- layer transition: f = elu(acc_in); acc_out = f@root+bias; y = f@b2
template<int MI>
__global__ void __launch_bounds__(256)
trans_kernel(const float* __restrict__ acc_in, float* __restrict__ fout,
             const float* __restrict__ root, const float* __restrict__ bias,
             const float* __restrict__ b2, float* __restrict__ acc_out) {
    __shared__ float f[4][MI];
    const int tid = threadIdx.x;
    const int n0 = blockIdx.x * 4;
    if (tid < 4 * MI) {
        int n = tid / MI, i = tid - n * MI;
        float v = eluf(acc_in[(size_t)(n0 + n) * MI + i]);
        f[n][i] = v;
        fout[(size_t)(n0 + n) * MI + i] = v;
    }
    __syncthreads();
    const int n = tid >> 6, o = tid & 63;
    float s = bias[o], y = 0.f;
#pragma unroll
    for (int i = 0; i < MI; i++) {
        float fv = f[n][i];
        s = fmaf(fv, root[i * 64 + o], s);
        y = fmaf(fv, b2[i * 64 + o], y);
    }
    acc_out[(size_t)(n0 + n) * 64 + o] = s;
    g_y[(size_t)(n0 + n) * 64 + o] = y;
}

// -------- layer-3 elu fused with graph pooling -----------------------------
__global__ void elu_pool_kernel(const float* __restrict__ acc) {
    int t = blockIdx.x * blockDim.x + threadIdx.x;
    if (t >= NN * 64) return;
    int n = t >> 6, o = t & 63;
    float v = eluf(acc[t]);
    int g = g_batch[n];
    atomicAdd(&g_sums[g * 64 + o], v);
    if (o == 0) atomicAdd(&g_cnt[g], 1.f);
}

// -------- message GEMM with FUSED edge-MLP prologue ------------------------
// The fp16 h A-tile is computed IN-KERNEL (no g_hA round trip):
//   stage ea (2.5KB) in smem; each thread owns one k-pair (w1/b1 in regs)
//   and 32 rows; h = relu(ea@w1+b1) stored straight into the A smem region.
// Store pattern: warp lanes = consecutive k-pairs at fixed row -> conflict-free.
// Compute overlaps the B-chunk cp.asyncs already in flight.
__device__ __forceinline__ void copyB(int cabs, uint32_t dst, int tid) {
    const unsigned char* gb = g_w2s + (size_t)cabs * 16384;
    for (int idx = tid; idx < 1024; idx += 256) {
        int r = idx >> 4, s = idx & 15;
        cp16(dst + r * 272 + s * 16, gb + r * 256 + s * 16);
    }
}

template<int M_IN, int M_OUT, int NC, int CBASE>
__global__ void __launch_bounds__(256, 2)
msg_mma_kernel(const float* __restrict__ xin, float* __restrict__ acc,
               const float* __restrict__ ea,
               const float* __restrict__ w1, const float* __restrict__ b1) {
    extern __shared__ char smem[];
    __shared__ float eas[640];
    const uint32_t sb = s2u(smem);
    const int tid = threadIdx.x, wid = tid >> 5, lane = tid & 31;
    const int tile = blockIdx.x;

    // kick off B copies first so they overlap the h compute
    copyB(CBASE, sb + SM_B, tid);
    cp_commit();
    if (NC > 1) { copyB(CBASE + 1, sb + SM_B + SM_BUF, tid); cp_commit(); }

    // stage ea slice (coalesced; guard tail)
    {
        const int gbase = tile * 640;
        for (int idx = tid; idx < 640; idx += 256)
            eas[idx] = (gbase + idx < NE * 5) ? ea[gbase + idx] : 0.f;
    }

    // per-thread w1/b1 for its k-pair
    const int kp = tid & 63;           // k = 2*kp, 2*kp+1
    const int k2 = kp * 2;
    float wv[10], bv0, bv1;
#pragma unroll
    for (int d = 0; d < 5; d++) {
        wv[2 * d]     = w1[d * HID + k2];
        wv[2 * d + 1] = w1[d * HID + k2 + 1];
    }
    bv0 = b1[k2]; bv1 = b1[k2 + 1];
    __syncthreads();                   // eas visible

    // compute h for 32 rows (rbase, rbase+4, ...), store fp16 pairs into A
    {
        const int rbase = tid >> 6;    // 0..3
        const int ecnt = min(128, NE - tile * 128);
#pragma unroll 8
        for (int j = 0; j < 32; j++) {
            const int r = rbase + 4 * j;
            uint32_t packed = 0;
            if (r < ecnt) {
                const float* a = eas + r * 5;
                float s0 = bv0, s1 = bv1;
                s0 = fmaf(a[0], wv[0], s0); s1 = fmaf(a[0], wv[1], s1);
                s0 = fmaf(a[1], wv[2], s0); s1 = fmaf(a[1], wv[3], s1);
                s0 = fmaf(a[2], wv[4], s0); s1 = fmaf(a[2], wv[5], s1);
                s0 = fmaf(a[3], wv[6], s0); s1 = fmaf(a[3], wv[7], s1);
                s0 = fmaf(a[4], wv[8], s0); s1 = fmaf(a[4], wv[9], s1);
                s0 = fmaxf(s0, 0.f); s1 = fmaxf(s1, 0.f);
                __half h0 = __float2half(s0), h1 = __float2half(s1);
                packed = ((uint32_t)__half_as_ushort(h1) << 16) | __half_as_ushort(h0);
            }
            *(uint32_t*)(smem + r * 272 + kp * 4) = packed;
        }
    }

    const int m0 = wid * 16;
    const int r0 = lane >> 2;
    const int e0 = tile * 128 + m0 + r0;
    const int e1 = e0 + 8;
    int src0 = 0, dst0 = -1, src1 = 0, dst1 = -1;
    if (e0 < NE) { src0 = g_src[e0]; dst0 = g_dst[e0]; }
    if (e1 < NE) { src1 = g_src[e1]; dst1 = g_dst[e1]; }

    const uint32_t lrow = (lane & 15);
    const uint32_t kh16 = (lane >> 4) * 16;

    float av[8][4];
#pragma unroll
    for (int nb = 0; nb < 8; nb++)
#pragma unroll
        for (int q = 0; q < 4; q++) av[nb][q] = 0.f;

    for (int c = 0; c < NC; c++) {
        if (c + 1 == NC) cp_wait<0>(); else cp_wait<1>();
        __syncthreads();               // B chunk + (c==0) A stores visible

        const uint32_t Bb = sb + SM_B + (uint32_t)(c & 1) * SM_BUF;
        float d[8][4];
#pragma unroll
        for (int nb = 0; nb < 8; nb++)
#pragma unroll
            for (int q = 0; q < 4; q++) d[nb][q] = 0.f;

#pragma unroll
        for (int ks = 0; ks < 8; ks++) {
            uint32_t a[4];
            ldsm4(a, sb + (m0 + lrow) * 272 + ks * 32 + kh16);
#pragma unroll
            for (int nb2 = 0; nb2 < 4; nb2++) {
                uint32_t b[4];
                ldsm4(b, Bb + (nb2 * 16 + lrow) * 272 + ks * 32 + kh16);
                mma16816(d[2 * nb2],     a, b[0], b[2]);
                mma16816(d[2 * nb2 + 1], a, b[1], b[3]);
            }
        }

        if constexpr (M_OUT == 64) {
            const float xs0 = xin[(size_t)src0 * M_IN + c];
            const float xs1 = xin[(size_t)src1 * M_IN + c];
#pragma unroll
            for (int nb = 0; nb < 8; nb++) {
                av[nb][0] = fmaf(xs0, d[nb][0], av[nb][0]);
                av[nb][1] = fmaf(xs0, d[nb][1], av[nb][1]);
                av[nb][2] = fmaf(xs1, d[nb][2], av[nb][2]);
                av[nb][3] = fmaf(xs1, d[nb][3], av[nb][3]);
            }
        } else {
            const int i0 = min(2 * c, M_IN - 1), i1 = min(2 * c + 1, M_IN - 1);
            const float x00 = xin[(size_t)src0 * M_IN + i0];
            const float x01 = xin[(size_t)src0 * M_IN + i1];
            const float x10 = xin[(size_t)src1 * M_IN + i0];
            const float x11 = xin[(size_t)src1 * M_IN + i1];
#pragma unroll
            for (int nb = 0; nb < 8; nb++) {
                const float xsa = (nb < 4) ? x00 : x01;
                const float xsb = (nb < 4) ? x10 : x11;
                av[nb][0] = fmaf(xsa, d[nb][0], av[nb][0]);
                av[nb][1] = fmaf(xsa, d[nb][1], av[nb][1]);
                av[nb][2] = fmaf(xsb, d[nb][2], av[nb][2]);
                av[nb][3] = fmaf(xsb, d[nb][3], av[nb][3]);
            }
        }

        __syncthreads();
        if (c + 2 < NC) { copyB(CBASE + c + 2, sb + SM_B + (uint32_t)(c & 1) * SM_BUF, tid); cp_commit(); }
    }

    const int oc = (lane & 3) * 2;
    if constexpr (M_OUT == 64) {
#pragma unroll
        for (int nb = 0; nb < 8; nb++) {
            const int o = nb * 8 + oc;
            if (dst0 >= 0) {
                atomicAdd(acc + (size_t)dst0 * 64 + o,     av[nb][0] + g_y[(size_t)src0 * 64 + o]);
                atomicAdd(acc + (size_t)dst0 * 64 + o + 1, av[nb][1] + g_y[(size_t)src0 * 64 + o + 1]);
            }
            if (dst1 >= 0) {
                atomicAdd(acc + (size_t)dst1 * 64 + o,     av[nb][2] + g_y[(size_t)src1 * 64 + o]);
                atomicAdd(acc + (size_t)dst1 * 64 + o + 1, av[nb][3] + g_y[(size_t)src1 * 64 + o + 1]);
            }
        }
    } else {
#pragma unroll
        for (int nb = 0; nb < 4; nb++) {
            const int o = nb * 8 + oc;
            if (dst0 >= 0) {
                atomicAdd(acc + (size_t)dst0 * 32 + o,     av[nb][0] + av[nb + 4][0] + g_y[(size_t)src0 * 32 + o]);
                atomicAdd(acc + (size_t)dst0 * 32 + o + 1, av[nb][1] + av[nb + 4][1] + g_y[(size_t)src0 * 32 + o + 1]);
            }
            if (dst1 >= 0) {
                atomicAdd(acc + (size_t)dst1 * 32 + o,     av[nb][2] + av[nb + 4][2] + g_y[(size_t)src1 * 32 + o]);
                atomicAdd(acc + (size_t)dst1 * 32 + o + 1, av[nb][3] + av[nb + 4][3] + g_y[(size_t)src1 * 32 + o + 1]);
            }
        }
    }
}

// ---------------- final MLP -------------------------------------------------
__global__ void __launch_bounds__(128)
mlp_kernel(const float* __restrict__ f1w, const float* __restrict__ f1b,
           const float* __restrict__ f2w, const float* __restrict__ f2b,
           const float* __restrict__ f3w, const float* __restrict__ f3b,
           float* __restrict__ out) {
    int g = blockIdx.x * blockDim.x + threadIdx.x;
    if (g >= NG) return;
    float inv = 1.f / fmaxf(g_cnt[g], 1.f);
    const float* sr = g_sums + g * 64;
    float h1[32];
#pragma unroll
    for (int j = 0; j < 32; j++) {
        float s = 0.f;
#pragma unroll
        for (int i = 0; i < 64; i++) s = fmaf(sr[i], f1w[i * 32 + j], s);
        h1[j] = eluf(fmaf(s, inv, f1b[j]));
    }
    float h2[16];
#pragma unroll
    for (int j = 0; j < 16; j++) {
        float s = f2b[j];
#pragma unroll
        for (int i = 0; i < 32; i++) s = fmaf(h1[i], f2w[i * 16 + j], s);
        h2[j] = eluf(s);
    }
    float s = f3b[0];
#pragma unroll
    for (int i = 0; i < 16; i++) s = fmaf(h2[i], f3w[i], s);
    out[g] = s;
}

// ---------------- driver ----------------------------------------------------
extern "C" void kernel_launch(void* const* d_in, const int* in_sizes, int n_in,
                              void* d_out, int out_size) {
    const float* x   = (const float*)d_in[0];
    const void*  ei  = d_in[1];
    const float* ea  = (const float*)d_in[2];
    const void*  bat = d_in[3];
    const float* W[24];
    for (int i = 0; i < 24; i++) W[i] = (const float*)d_in[4 + i];
    float* out = (float*)d_out;

    float *fa, *fb, *acc, *acc2;
    cudaGetSymbolAddress((void**)&fa, g_fa);
    cudaGetSymbolAddress((void**)&fb, g_fb);
    cudaGetSymbolAddress((void**)&acc, g_acc);
    cudaGetSymbolAddress((void**)&acc2, g_acc2);

    cudaFuncSetAttribute(msg_mma_kernel<13, 32, 7, 0>,   cudaFuncAttributeMaxDynamicSharedMemorySize, SMEM_BYTES);
    cudaFuncSetAttribute(msg_mma_kernel<32, 64, 32, 7>,  cudaFuncAttributeMaxDynamicSharedMemorySize, SMEM_BYTES);
    cudaFuncSetAttribute(msg_mma_kernel<64, 64, 64, 39>, cudaFuncAttributeMaxDynamicSharedMemorySize, SMEM_BYTES);

    detect_kernel<<<1, 32>>>((const long long*)ei);
    convert_kernel<<<(NG * 64 + 255) / 256, 256>>>(ei, bat);   // also zeroes pooling buffers
    w2prep_all_kernel<<<(103 * 8192 + 255) / 256, 256>>>(W[2], W[8], W[14]);

    // layer 1: 13 -> 32
    rootxb2_kernel<13, 32><<<(NN * 32 + 255) / 256, 256>>>(x, W[4], W[5], W[3], acc);
    msg_mma_kernel<13, 32, 7, 0><<<NTILES, 256, SMEM_BYTES>>>(x, acc, ea, W[0], W[1]);

    // transition 1->2, then layer 2
    trans_kernel<32><<<NN / 4, 256>>>(acc, fa, W[10], W[11], W[9], acc2);
    msg_mma_kernel<32, 64, 32, 7><<<NTILES, 256, SMEM_BYTES>>>(fa, acc2, ea, W[6], W[7]);

    // transition 2->3, then layer 3
    trans_kernel<64><<<NN / 4, 256>>>(acc2, fb, W[16], W[17], W[15], acc);
    msg_mma_kernel<64, 64, 64, 39><<<NTILES, 256, SMEM_BYTES>>>(fb, acc, ea, W[12], W[13]);

    // layer-3 elu + pooling, then head
    elu_pool_kernel<<<(NN * 64 + 255) / 256, 256>>>(acc);
    mlp_kernel<<<(NG + 127) / 128, 128>>>(W[18], W[19], W[20], W[21], W[22], W[23], out);
}

// round 12
// speedup vs baseline: 1.1858x; 1.0209x over previous
#include <cuda_runtime.h>
#include <cuda_fp16.h>
#include <math.h>
#include <stdint.h>

#define NE 50000
#define NN 25000
#define NG 1024
#define HID 128
#define NTILES 391

// msg smem (dynamic): A [128x272B] | B buf0 | B buf1 | B buf2 (each 64x272B)
#define SM_B      34816
#define SM_BUF    17408
#define SMEM_BYTES 87040

__device__ __align__(256) unsigned char g_w2s[103 * 16384];   // all layers' fp16 w2T chunks [64x256B]
__device__ float g_fa[NN * 64];
__device__ float g_fb[NN * 64];
__device__ float g_acc[NN * 64];
__device__ float g_acc2[NN * 64];
__device__ float g_y[NN * 64];        // x @ b2 per node
__device__ float g_sums[NG * 64];
__device__ float g_cnt[NG];
__device__ int g_src[NE], g_dst[NE], g_batch[NN];

__device__ __forceinline__ float eluf(float v) { return v > 0.f ? v : expm1f(v); }
__device__ __forceinline__ uint32_t s2u(const void* p) {
    uint32_t a;
    asm("{ .reg .u64 t; cvta.to.shared.u64 t, %1; cvt.u32.u64 %0, t; }" : "=r"(a) : "l"(p));
    return a;
}
__device__ __forceinline__ void cp16(uint32_t s, const void* g) {
    asm volatile("cp.async.cg.shared.global [%0], [%1], 16;" :: "r"(s), "l"(g));
}
__device__ __forceinline__ void cp_commit() { asm volatile("cp.async.commit_group;" ::: "memory"); }
template<int N> __device__ __forceinline__ void cp_wait() { asm volatile("cp.async.wait_group %0;" :: "n"(N) : "memory"); }
__device__ __forceinline__ void ldsm4(uint32_t* r, uint32_t a) {
    asm volatile("ldmatrix.sync.aligned.m8n8.x4.shared.b16 {%0,%1,%2,%3}, [%4];"
                 : "=r"(r[0]), "=r"(r[1]), "=r"(r[2]), "=r"(r[3]) : "r"(a));
}
__device__ __forceinline__ void mma16816(float* d, const uint32_t* a, uint32_t b0, uint32_t b1) {
    asm volatile("mma.sync.aligned.m16n8k16.row.col.f32.f16.f16.f32 "
                 "{%0,%1,%2,%3}, {%4,%5,%6,%7}, {%8,%9}, {%0,%1,%2,%3};"
                 : "+f"(d[0]), "+f"(d[1]), "+f"(d[2]), "+f"(d[3])
                 : "r"(a[0]), "r"(a[1]), "r"(a[2]), "r"(a[3]), "r"(b0), "r"(b1));
}

// ---------------- convert (detect inlined) + pool-zero ---------------------
// dtype check: reinterpret first 32 int64 slots; int32 index pairs have a
// nonzero hi word somewhere in the first 64 values -> value >= 2^32 -> "32".
// Broadcast loads (all threads same addresses), L1-hit, uniform result.
__global__ void convert_kernel(const void* __restrict__ ei, const void* __restrict__ bat) {
    const long long* e64 = (const long long*)ei;
    int is64 = 1;
#pragma unroll
    for (int i = 0; i < 32; i++) {
        long long v = e64[i];
        if (v < 0 || v >= (long long)NN) { is64 = 0; break; }
    }
    int t = blockIdx.x * blockDim.x + threadIdx.x;
    if (t < NE) {
        if (is64) { g_src[t] = (int)((const long long*)ei)[t]; g_dst[t] = (int)((const long long*)ei)[NE + t]; }
        else      { g_src[t] = ((const int*)ei)[t];            g_dst[t] = ((const int*)ei)[NE + t]; }
    }
    if (t < NN) g_batch[t] = is64 ? (int)((const long long*)bat)[t] : ((const int*)bat)[t];
    if (t < NG * 64) g_sums[t] = 0.f;
    if (t < NG) g_cnt[t] = 0.f;
}

// -------- all 3 layers' w2 -> fp16 B chunk tiles (one launch) --------------
__global__ void w2prep_all_kernel(const float* __restrict__ w2a,
                                  const float* __restrict__ w2b,
                                  const float* __restrict__ w2c) {
    int t = blockIdx.x * blockDim.x + threadIdx.x;
    if (t >= 103 * 8192) return;
    int c = t >> 13, rem = t & 8191, r = rem >> 7, k = rem & 127;
    const float* w2; int cb, sz;
    if (c < 7)       { w2 = w2a; cb = 0;  sz = 13 * 32; }
    else if (c < 39) { w2 = w2b; cb = 7;  sz = 32 * 64; }
    else             { w2 = w2c; cb = 39; sz = 64 * 64; }
    int n = (c - cb) * 64 + r;
    float v = (n < sz) ? w2[k * sz + n] : 0.f;
    *(__half*)(g_w2s + (size_t)c * 16384 + r * 256 + k * 2) = __float2half(v);
}

// -------- layer-1 entry: acc = x @ root + bias; g_y = x @ b2 ---------------
template<int M_IN, int M_OUT>
__global__ void rootxb2_kernel(const float* __restrict__ x, const float* __restrict__ root,
                               const float* __restrict__ bias, const float* __restrict__ b2,
                               float* __restrict__ acc) {
    int t = blockIdx.x * blockDim.x + threadIdx.x;
    if (t >= NN * M_OUT) return;
    int n = t / M_OUT, o = t - n * M_OUT;
    const float* xr = x + n * M_IN;
    float s = bias[o], y = 0.f;
#pragma unroll
    for (int i = 0; i < M_IN; i++) {
        float xv = xr[i];
        s = fmaf(xv, root[i * M_OUT + o], s);
        y = fmaf(xv, b2[i * M_OUT + o], y);
    }
    acc[t] = s;
    g_y[t] = y;
}

// -------- layer transition: f = elu(acc_in); acc_out = f@root+bias; y = f@b2
template<int MI>
__global__ void __launch_bounds__(256)
trans_kernel(const float* __restrict__ acc_in, float* __restrict__ fout,
             const float* __restrict__ root, const float* __restrict__ bias,
             const float* __restrict__ b2, float* __restrict__ acc_out) {
    __shared__ float f[4][MI];
    const int tid = threadIdx.x;
    const int n0 = blockIdx.x * 4;
    if (tid < 4 * MI) {
        int n = tid / MI, i = tid - n * MI;
        float v = eluf(acc_in[(size_t)(n0 + n) * MI + i]);
        f[n][i] = v;
        fout[(size_t)(n0 + n) * MI + i] = v;
    }
    __syncthreads();
    const int n = tid >> 6, o = tid & 63;
    float s = bias[o], y = 0.f;
#pragma unroll
    for (int i = 0; i < MI; i++) {
        float fv = f[n][i];
        s = fmaf(fv, root[i * 64 + o], s);
        y = fmaf(fv, b2[i * 64 + o], y);
    }
    acc_out[(size_t)(n0 + n) * 64 + o] = s;
    g_y[(size_t)(n0 + n) * 64 + o] = y;
}

// -------- layer-3 elu + pooling with run-length aggregation ----------------
// batch is SORTED (~24 nodes/graph). Each thread owns output column o and a
// strip of 8 consecutive nodes: accumulate while graph id constant, flush on
// change -> ~4-8x fewer same-address atomics (L2 atomic ALU serializes per
// address, so collision count is the cost driver).
__global__ void __launch_bounds__(256)
elu_pool_kernel(const float* __restrict__ acc) {
    const int tid = threadIdx.x;
    const int o = tid & 63;
    const int grp = tid >> 6;                 // 0..3
    const int n0 = blockIdx.x * 32 + grp * 8; // this thread's 8-node strip
    float s = 0.f;
    int curg = -1;
    for (int j = 0; j < 8; j++) {
        const int n = n0 + j;
        if (n >= NN) break;
        const int g = g_batch[n];
        const float v = eluf(acc[(size_t)n * 64 + o]);
        if (g != curg) {
            if (curg >= 0) atomicAdd(&g_sums[curg * 64 + o], s);
            curg = g; s = v;
        } else s += v;
        if (o == 0 && (g != ((n + 1 < NN) ? g_batch[n + 1] : -2) || j == 7)) {} // cnt handled below
    }
    if (curg >= 0) atomicAdd(&g_sums[curg * 64 + o], s);
    // counts: one lane (o==0) per strip, run-length too
    if (o == 0) {
        float c = 0.f; int cg = -1;
        for (int j = 0; j < 8; j++) {
            const int n = n0 + j;
            if (n >= NN) break;
            const int g = g_batch[n];
            if (g != cg) { if (cg >= 0) atomicAdd(&g_cnt[cg], c); cg = g; c = 1.f; }
            else c += 1.f;
        }
        if (cg >= 0) atomicAdd(&g_cnt[cg], c);
    }
}

// -------- message GEMM with fused edge-MLP prologue, 3-buffer pipeline -----
// Second per-chunk __syncthreads removed: refill target (c+2)%3 was last read
// at chunk c-1, and all warps passed chunk c's barrier before the refill issue.
__device__ __forceinline__ void copyB(int cabs, uint32_t dst, int tid) {
    const unsigned char* gb = g_w2s + (size_t)cabs * 16384;
    for (int idx = tid; idx < 1024; idx += 256) {
        int r = idx >> 4, s = idx & 15;
        cp16(dst + r * 272 + s * 16, gb + r * 256 + s * 16);
    }
}

template<int M_IN, int M_OUT, int NC, int CBASE>
__global__ void __launch_bounds__(256, 2)
msg_mma_kernel(const float* __restrict__ xin, float* __restrict__ acc,
               const float* __restrict__ ea,
               const float* __restrict__ w1, const float* __restrict__ b1) {
    extern __shared__ char smem[];
    __shared__ float eas[640];
    const uint32_t sb = s2u(smem);
    const int tid = threadIdx.x, wid = tid >> 5, lane = tid & 31;
    const int tile = blockIdx.x;

    // kick off B copies first so they overlap the h compute
    copyB(CBASE, sb + SM_B, tid);
    cp_commit();
    if (NC > 1) { copyB(CBASE + 1, sb + SM_B + SM_BUF, tid); cp_commit(); }

    // stage ea slice (coalesced; guard tail)
    {
        const int gbase = tile * 640;
        for (int idx = tid; idx < 640; idx += 256)
            eas[idx] = (gbase + idx < NE * 5) ? ea[gbase + idx] : 0.f;
    }

    // per-thread w1/b1 for its k-pair
    const int kp = tid & 63;
    const int k2 = kp * 2;
    float wv[10], bv0, bv1;
#pragma unroll
    for (int d = 0; d < 5; d++) {
        wv[2 * d]     = w1[d * HID + k2];
        wv[2 * d + 1] = w1[d * HID + k2 + 1];
    }
    bv0 = b1[k2]; bv1 = b1[k2 + 1];
    __syncthreads();                   // eas visible

    // compute h tile -> A smem (fp16 pairs), conflict-free store pattern
    {
        const int rbase = tid >> 6;
        const int ecnt = min(128, NE - tile * 128);
#pragma unroll 8
        for (int j = 0; j < 32; j++) {
            const int r = rbase + 4 * j;
            uint32_t packed = 0;
            if (r < ecnt) {
                const float* a = eas + r * 5;
                float s0 = bv0, s1 = bv1;
                s0 = fmaf(a[0], wv[0], s0); s1 = fmaf(a[0], wv[1], s1);
                s0 = fmaf(a[1], wv[2], s0); s1 = fmaf(a[1], wv[3], s1);
                s0 = fmaf(a[2], wv[4], s0); s1 = fmaf(a[2], wv[5], s1);
                s0 = fmaf(a[3], wv[6], s0); s1 = fmaf(a[3], wv[7], s1);
                s0 = fmaf(a[4], wv[8], s0); s1 = fmaf(a[4], wv[9], s1);
                s0 = fmaxf(s0, 0.f); s1 = fmaxf(s1, 0.f);
                __half h0 = __float2half(s0), h1 = __float2half(s1);
                packed = ((uint32_t)__half_as_ushort(h1) << 16) | __half_as_ushort(h0);
            }
            *(uint32_t*)(smem + r * 272 + kp * 4) = packed;
        }
    }

    const int m0 = wid * 16;
    const int r0 = lane >> 2;
    const int e0 = tile * 128 + m0 + r0;
    const int e1 = e0 + 8;
    int src0 = 0, dst0 = -1, src1 = 0, dst1 = -1;
    if (e0 < NE) { src0 = g_src[e0]; dst0 = g_dst[e0]; }
    if (e1 < NE) { src1 = g_src[e1]; dst1 = g_dst[e1]; }

    const uint32_t lrow = (lane & 15);
    const uint32_t kh16 = (lane >> 4) * 16;

    float av[8][4];
#pragma unroll
    for (int nb = 0; nb < 8; nb++)
#pragma unroll
        for (int q = 0; q < 4; q++) av[nb][q] = 0.f;

    int bufc = 0;                      // (c % 3), maintained incrementally
    for (int c = 0; c < NC; c++) {
        if (c + 1 == NC) cp_wait<0>(); else cp_wait<1>();
        __syncthreads();               // chunk c's B + (c==0) A stores visible

        // refill chunk c+2 into buffer (c+2)%3 (read last at chunk c-1; safe)
        if (c + 2 < NC) {
            int b2i = bufc + 2; if (b2i >= 3) b2i -= 3;
            copyB(CBASE + c + 2, sb + SM_B + (uint32_t)b2i * SM_BUF, tid);
            cp_commit();
        }

        const uint32_t Bb = sb + SM_B + (uint32_t)bufc * SM_BUF;
        if (++bufc == 3) bufc = 0;
        float d[8][4];
#pragma unroll
        for (int nb = 0; nb < 8; nb++)
#pragma unroll
            for (int q = 0; q < 4; q++) d[nb][q] = 0.f;

#pragma unroll
        for (int ks = 0; ks < 8; ks++) {
            uint32_t a[4];
            ldsm4(a, sb + (m0 + lrow) * 272 + ks * 32 + kh16);
#pragma unroll
            for (int nb2 = 0; nb2 < 4; nb2++) {
                uint32_t b[4];
                ldsm4(b, Bb + (nb2 * 16 + lrow) * 272 + ks * 32 + kh16);
                mma16816(d[2 * nb2],     a, b[0], b[2]);
                mma16816(d[2 * nb2 + 1], a, b[1], b[3]);
            }
        }

        if constexpr (M_OUT == 64) {
            const float xs0 = xin[(size_t)src0 * M_IN + c];
            const float xs1 = xin[(size_t)src1 * M_IN + c];
#pragma unroll
            for (int nb = 0; nb < 8; nb++) {
                av[nb][0] = fmaf(xs0, d[nb][0], av[nb][0]);
                av[nb][1] = fmaf(xs0, d[nb][1], av[nb][1]);
                av[nb][2] = fmaf(xs1, d[nb][2], av[nb][2]);
                av[nb][3] = fmaf(xs1, d[nb][3], av[nb][3]);
            }
        } else {
            const int i0 = min(2 * c, M_IN - 1), i1 = min(2 * c + 1, M_IN - 1);
            const float x00 = xin[(size_t)src0 * M_IN + i0];
            const float x01 = xin[(size_t)src0 * M_IN + i1];
            const float x10 = xin[(size_t)src1 * M_IN + i0];
            const float x11 = xin[(size_t)src1 * M_IN + i1];
#pragma unroll
            for (int nb = 0; nb < 8; nb++) {
                const float xsa = (nb < 4) ? x00 : x01;
                const float xsb = (nb < 4) ? x10 : x11;
                av[nb][0] = fmaf(xsa, d[nb][0], av[nb][0]);
                av[nb][1] = fmaf(xsa, d[nb][1], av[nb][1]);
                av[nb][2] = fmaf(xsb, d[nb][2], av[nb][2]);
                av[nb][3] = fmaf(xsb, d[nb][3], av[nb][3]);
            }
        }
        // no trailing __syncthreads: next chunk's cp_wait + barrier protects
    }

    const int oc = (lane & 3) * 2;
    if constexpr (M_OUT == 64) {
#pragma unroll
        for (int nb = 0; nb < 8; nb++) {
            const int o = nb * 8 + oc;
            if (dst0 >= 0) {
                atomicAdd(acc + (size_t)dst0 * 64 + o,     av[nb][0] + g_y[(size_t)src0 * 64 + o]);
                atomicAdd(acc + (size_t)dst0 * 64 + o + 1, av[nb][1] + g_y[(size_t)src0 * 64 + o + 1]);
            }
            if (dst1 >= 0) {
                atomicAdd(acc + (size_t)dst1 * 64 + o,     av[nb][2] + g_y[(size_t)src1 * 64 + o]);
                atomicAdd(acc + (size_t)dst1 * 64 + o + 1, av[nb][3] + g_y[(size_t)src1 * 64 + o + 1]);
            }
        }
    } else {
#pragma unroll
        for (int nb = 0; nb < 4; nb++) {
            const int o = nb * 8 + oc;
            if (dst0 >= 0) {
                atomicAdd(acc + (size_t)dst0 * 32 + o,     av[nb][0] + av[nb + 4][0] + g_y[(size_t)src0 * 32 + o]);
                atomicAdd(acc + (size_t)dst0 * 32 + o + 1, av[nb][1] + av[nb + 4][1] + g_y[(size_t)src0 * 32 + o + 1]);
            }
            if (dst1 >= 0) {
                atomicAdd(acc + (size_t)dst1 * 32 + o,     av[nb][2] + av[nb + 4][2] + g_y[(size_t)src1 * 32 + o]);
                atomicAdd(acc + (size_t)dst1 * 32 + o + 1, av[nb][3] + av[nb + 4][3] + g_y[(size_t)src1 * 32 + o + 1]);
            }
        }
    }
}

// ---------------- final MLP -------------------------------------------------
__global__ void __launch_bounds__(128)
mlp_kernel(const float* __restrict__ f1w, const float* __restrict__ f1b,
           const float* __restrict__ f2w, const float* __restrict__ f2b,
           const float* __restrict__ f3w, const float* __restrict__ f3b,
           float* __restrict__ out) {
    int g = blockIdx.x * blockDim.x + threadIdx.x;
    if (g >= NG) return;
    float inv = 1.f / fmaxf(g_cnt[g], 1.f);
    const float* sr = g_sums + g * 64;
    float h1[32];
#pragma unroll
    for (int j = 0; j < 32; j++) {
        float s = 0.f;
#pragma unroll
        for (int i = 0; i < 64; i++) s = fmaf(sr[i], f1w[i * 32 + j], s);
        h1[j] = eluf(fmaf(s, inv, f1b[j]));
    }
    float h2[16];
#pragma unroll
    for (int j = 0; j < 16; j++) {
        float s = f2b[j];
#pragma unroll
        for (int i = 0; i < 32; i++) s = fmaf(h1[i], f2w[i * 16 + j], s);
        h2[j] = eluf(s);
    }
    float s = f3b[0];
#pragma unroll
    for (int i = 0; i < 16; i++) s = fmaf(h2[i], f3w[i], s);
    out[g] = s;
}

// ---------------- driver ----------------------------------------------------
extern "C" void kernel_launch(void* const* d_in, const int* in_sizes, int n_in,
                              void* d_out, int out_size) {
    const float* x   = (const float*)d_in[0];
    const void*  ei  = d_in[1];
    const float* ea  = (const float*)d_in[2];
    const void*  bat = d_in[3];
    const float* W[24];
    for (int i = 0; i < 24; i++) W[i] = (const float*)d_in[4 + i];
    float* out = (float*)d_out;

    float *fa, *fb, *acc, *acc2;
    cudaGetSymbolAddress((void**)&fa, g_fa);
    cudaGetSymbolAddress((void**)&fb, g_fb);
    cudaGetSymbolAddress((void**)&acc, g_acc);
    cudaGetSymbolAddress((void**)&acc2, g_acc2);

    cudaFuncSetAttribute(msg_mma_kernel<13, 32, 7, 0>,   cudaFuncAttributeMaxDynamicSharedMemorySize, SMEM_BYTES);
    cudaFuncSetAttribute(msg_mma_kernel<32, 64, 32, 7>,  cudaFuncAttributeMaxDynamicSharedMemorySize, SMEM_BYTES);
    cudaFuncSetAttribute(msg_mma_kernel<64, 64, 64, 39>, cudaFuncAttributeMaxDynamicSharedMemorySize, SMEM_BYTES);

    convert_kernel<<<(NG * 64 + 255) / 256, 256>>>(ei, bat);   // detect inlined; zeroes pooling
    w2prep_all_kernel<<<(103 * 8192 + 255) / 256, 256>>>(W[2], W[8], W[14]);

    // layer 1: 13 -> 32
    rootxb2_kernel<13, 32><<<(NN * 32 + 255) / 256, 256>>>(x, W[4], W[5], W[3], acc);
    msg_mma_kernel<13, 32, 7, 0><<<NTILES, 256, SMEM_BYTES>>>(x, acc, ea, W[0], W[1]);

    // transition 1->2, then layer 2
    trans_kernel<32><<<NN / 4, 256>>>(acc, fa, W[10], W[11], W[9], acc2);
    msg_mma_kernel<32, 64, 32, 7><<<NTILES, 256, SMEM_BYTES>>>(fa, acc2, ea, W[6], W[7]);

    // transition 2->3, then layer 3
    trans_kernel<64><<<NN / 4, 256>>>(acc2, fb, W[16], W[17], W[15], acc);
    msg_mma_kernel<64, 64, 64, 39><<<NTILES, 256, SMEM_BYTES>>>(fb, acc, ea, W[12], W[13]);

    // layer-3 elu + pooling (run-length aggregated), then head
    elu_pool_kernel<<<(NN + 31) / 32, 256>>>(acc);
    mlp_kernel<<<(NG + 127) / 128, 128>>>(W[18], W[19], W[20], W[21], W[22], W[23], out);
}